// round 1
// baseline (speedup 1.0000x reference)
#include <cuda_runtime.h>

#define M_SLOTS 16
#define KEY_DIM 1024

// softmax weights, produced by weights_kernel, consumed by wsum_kernel
__device__ float g_w[M_SLOTS];

// ---------------------------------------------------------------------------
// Kernel 1: cosine similarity + softmax over the 16 memory slots.
// 16 warps (512 threads), warp m handles slot m. Each warp also redundantly
// computes ||task_emb|| (cheap: 1024 floats, L1-resident after first warp).
// ---------------------------------------------------------------------------
__global__ void weights_kernel(const float* __restrict__ task_emb,
                               const float* __restrict__ K_memory) {
    __shared__ float s_cos[M_SLOTS];
    const int warp = threadIdx.x >> 5;
    const int lane = threadIdx.x & 31;

    const float* key = K_memory + warp * KEY_DIM;
    float dot = 0.f, kk = 0.f, tt = 0.f;
    #pragma unroll 8
    for (int k = lane; k < KEY_DIM; k += 32) {
        float t = task_emb[k];
        float km = key[k];
        dot = fmaf(t, km, dot);
        kk  = fmaf(km, km, kk);
        tt  = fmaf(t, t, tt);
    }
    #pragma unroll
    for (int off = 16; off > 0; off >>= 1) {
        dot += __shfl_down_sync(0xffffffffu, dot, off);
        kk  += __shfl_down_sync(0xffffffffu, kk,  off);
        tt  += __shfl_down_sync(0xffffffffu, tt,  off);
    }
    if (lane == 0) {
        float denom = fmaxf(sqrtf(tt) * sqrtf(kk), 1e-6f);
        s_cos[warp] = dot / denom;
    }
    __syncthreads();

    if (threadIdx.x == 0) {
        float mx = -1e30f;
        #pragma unroll
        for (int m = 0; m < M_SLOTS; m++) mx = fmaxf(mx, s_cos[m]);
        float e[M_SLOTS];
        float sum = 0.f;
        #pragma unroll
        for (int m = 0; m < M_SLOTS; m++) {
            e[m] = __expf(s_cos[m] - mx);
            sum += e[m];
        }
        float inv = 1.0f / sum;
        #pragma unroll
        for (int m = 0; m < M_SLOTS; m++) g_w[m] = e[m] * inv;
    }
}

// ---------------------------------------------------------------------------
// Kernel 2: out[i] = sum_m w[m] * V[m][i], vectorized float4.
// One float4 per thread; 16 independent LDG.128 per thread (MLP=16).
// ---------------------------------------------------------------------------
__global__ void __launch_bounds__(256) wsum_kernel(const float4* __restrict__ V,
                                                   float4* __restrict__ out,
                                                   int nv4) {
    int i = blockIdx.x * blockDim.x + threadIdx.x;
    if (i >= nv4) return;

    float w[M_SLOTS];
    #pragma unroll
    for (int m = 0; m < M_SLOTS; m++) w[m] = g_w[m];

    float4 acc = make_float4(0.f, 0.f, 0.f, 0.f);
    #pragma unroll
    for (int m = 0; m < M_SLOTS; m++) {
        float4 v = V[(size_t)m * (size_t)nv4 + (size_t)i];
        acc.x = fmaf(w[m], v.x, acc.x);
        acc.y = fmaf(w[m], v.y, acc.y);
        acc.z = fmaf(w[m], v.z, acc.z);
        acc.w = fmaf(w[m], v.w, acc.w);
    }
    out[i] = acc;
}

// ---------------------------------------------------------------------------
// Launch contract
// Inputs (metadata order): task_emb [1,1024] f32, K_memory [16,1024] f32,
//                          V0 [16,1024,1024] f32, V1 [16,1024,4096] f32
// Output: rec0 [1024,1024] f32 followed by rec1 [1024,4096] f32
// ---------------------------------------------------------------------------
extern "C" void kernel_launch(void* const* d_in, const int* in_sizes, int n_in,
                              void* d_out, int out_size) {
    const float* task_emb = (const float*)d_in[0];
    const float* K_memory = (const float*)d_in[1];
    const float* V0       = (const float*)d_in[2];
    const float* V1       = (const float*)d_in[3];
    float* out = (float*)d_out;

    // per-slot element counts (derive from in_sizes for robustness)
    const int n0 = in_sizes[2] / M_SLOTS;   // 1024*1024
    const int n1 = in_sizes[3] / M_SLOTS;   // 1024*4096
    const int nv4_0 = n0 / 4;
    const int nv4_1 = n1 / 4;

    weights_kernel<<<1, 512>>>(task_emb, K_memory);

    wsum_kernel<<<(nv4_0 + 255) / 256, 256>>>((const float4*)V0,
                                              (float4*)out, nv4_0);
    wsum_kernel<<<(nv4_1 + 255) / 256, 256>>>((const float4*)V1,
                                              (float4*)(out + n0), nv4_1);
}

// round 2
// speedup vs baseline: 1.0335x; 1.0335x over previous
#include <cuda_runtime.h>

#define M_SLOTS 16
#define KEY_DIM 1024

// softmax weights, produced by weights_kernel, consumed by wsum_fused_kernel
__device__ float g_w[M_SLOTS];

// ---------------------------------------------------------------------------
// Kernel 1: cosine similarity + softmax over the 16 memory slots.
// 512 threads = 16 warps; warp m handles slot m. float4 loads so each thread
// front-batches 16 LDG.128 (8 key + 8 task) -> one DRAM round-trip.
// ---------------------------------------------------------------------------
__global__ void __launch_bounds__(512) weights_kernel(
        const float* __restrict__ task_emb,
        const float* __restrict__ K_memory) {
    __shared__ float s_cos[M_SLOTS];
    const int warp = threadIdx.x >> 5;
    const int lane = threadIdx.x & 31;

    const float4* t4 = (const float4*)task_emb;                 // 256 float4
    const float4* k4 = (const float4*)(K_memory + warp * KEY_DIM);

    float dot = 0.f, kk = 0.f, tt = 0.f;
    #pragma unroll
    for (int j = 0; j < 8; j++) {
        float4 t  = t4[lane + 32 * j];
        float4 km = k4[lane + 32 * j];
        dot = fmaf(t.x, km.x, dot); dot = fmaf(t.y, km.y, dot);
        dot = fmaf(t.z, km.z, dot); dot = fmaf(t.w, km.w, dot);
        kk  = fmaf(km.x, km.x, kk); kk  = fmaf(km.y, km.y, kk);
        kk  = fmaf(km.z, km.z, kk); kk  = fmaf(km.w, km.w, kk);
        tt  = fmaf(t.x,  t.x,  tt); tt  = fmaf(t.y,  t.y,  tt);
        tt  = fmaf(t.z,  t.z,  tt); tt  = fmaf(t.w,  t.w,  tt);
    }
    #pragma unroll
    for (int off = 16; off > 0; off >>= 1) {
        dot += __shfl_down_sync(0xffffffffu, dot, off);
        kk  += __shfl_down_sync(0xffffffffu, kk,  off);
        tt  += __shfl_down_sync(0xffffffffu, tt,  off);
    }
    if (lane == 0) {
        float denom = fmaxf(sqrtf(tt) * sqrtf(kk), 1e-6f);
        s_cos[warp] = dot / denom;
    }
    __syncthreads();

    if (threadIdx.x == 0) {
        float mx = -1e30f;
        #pragma unroll
        for (int m = 0; m < M_SLOTS; m++) mx = fmaxf(mx, s_cos[m]);
        float e[M_SLOTS];
        float sum = 0.f;
        #pragma unroll
        for (int m = 0; m < M_SLOTS; m++) {
            e[m] = __expf(s_cos[m] - mx);
            sum += e[m];
        }
        float inv = 1.0f / sum;
        #pragma unroll
        for (int m = 0; m < M_SLOTS; m++) g_w[m] = e[m] * inv;
    }
}

// ---------------------------------------------------------------------------
// Kernel 2 (fused): one grid covers both V0 and V1 segments.
// out[i] = sum_m w[m] * V[m][i], one float4 per thread, 16 LDG.128 MLP.
// ---------------------------------------------------------------------------
__global__ void __launch_bounds__(256) wsum_fused_kernel(
        const float4* __restrict__ V0,
        const float4* __restrict__ V1,
        float4* __restrict__ out,
        int nv4_0, int nv4_1) {
    int i = blockIdx.x * blockDim.x + threadIdx.x;

    const float4* __restrict__ V;
    float4* __restrict__ dst;
    int idx, stride;
    if (i < nv4_0) {
        V = V0; idx = i; stride = nv4_0; dst = out + i;
    } else {
        int j = i - nv4_0;
        if (j >= nv4_1) return;
        V = V1; idx = j; stride = nv4_1; dst = out + nv4_0 + j;
    }

    float w[M_SLOTS];
    #pragma unroll
    for (int m = 0; m < M_SLOTS; m++) w[m] = g_w[m];

    float4 acc = make_float4(0.f, 0.f, 0.f, 0.f);
    #pragma unroll
    for (int m = 0; m < M_SLOTS; m++) {
        float4 v = V[(size_t)m * (size_t)stride + (size_t)idx];
        acc.x = fmaf(w[m], v.x, acc.x);
        acc.y = fmaf(w[m], v.y, acc.y);
        acc.z = fmaf(w[m], v.z, acc.z);
        acc.w = fmaf(w[m], v.w, acc.w);
    }
    *dst = acc;
}

// ---------------------------------------------------------------------------
// Launch contract
// Inputs (metadata order): task_emb [1,1024] f32, K_memory [16,1024] f32,
//                          V0 [16,1024,1024] f32, V1 [16,1024,4096] f32
// Output: rec0 [1024,1024] f32 followed by rec1 [1024,4096] f32
// ---------------------------------------------------------------------------
extern "C" void kernel_launch(void* const* d_in, const int* in_sizes, int n_in,
                              void* d_out, int out_size) {
    const float* task_emb = (const float*)d_in[0];
    const float* K_memory = (const float*)d_in[1];
    const float* V0       = (const float*)d_in[2];
    const float* V1       = (const float*)d_in[3];
    float* out = (float*)d_out;

    const int n0 = in_sizes[2] / M_SLOTS;   // 1024*1024
    const int n1 = in_sizes[3] / M_SLOTS;   // 1024*4096
    const int nv4_0 = n0 / 4;
    const int nv4_1 = n1 / 4;
    const int total = nv4_0 + nv4_1;

    weights_kernel<<<1, 512>>>(task_emb, K_memory);

    wsum_fused_kernel<<<(total + 255) / 256, 256>>>(
        (const float4*)V0, (const float4*)V1, (float4*)out, nv4_0, nv4_1);
}

// round 4
// speedup vs baseline: 1.0407x; 1.0070x over previous
#include <cuda_runtime.h>

#define M_SLOTS 16
#define KEY_DIM 1024

// softmax weights, produced by weights_kernel, consumed by wsum_fused_kernel
__device__ float g_w[M_SLOTS];

// ---------------------------------------------------------------------------
// Kernel 1: cosine similarity + softmax over the 16 memory slots.
// 512 threads = 16 warps; warp m handles slot m; float4 loads.
// ---------------------------------------------------------------------------
__global__ void __launch_bounds__(512) weights_kernel(
        const float* __restrict__ task_emb,
        const float* __restrict__ K_memory) {
    __shared__ float s_cos[M_SLOTS];
    const int warp = threadIdx.x >> 5;
    const int lane = threadIdx.x & 31;

    const float4* t4 = (const float4*)task_emb;                 // 256 float4
    const float4* k4 = (const float4*)(K_memory + warp * KEY_DIM);

    float dot = 0.f, kk = 0.f, tt = 0.f;
    #pragma unroll
    for (int j = 0; j < 8; j++) {
        float4 t  = t4[lane + 32 * j];
        float4 km = k4[lane + 32 * j];
        dot = fmaf(t.x, km.x, dot); dot = fmaf(t.y, km.y, dot);
        dot = fmaf(t.z, km.z, dot); dot = fmaf(t.w, km.w, dot);
        kk  = fmaf(km.x, km.x, kk); kk  = fmaf(km.y, km.y, kk);
        kk  = fmaf(km.z, km.z, kk); kk  = fmaf(km.w, km.w, kk);
        tt  = fmaf(t.x,  t.x,  tt); tt  = fmaf(t.y,  t.y,  tt);
        tt  = fmaf(t.z,  t.z,  tt); tt  = fmaf(t.w,  t.w,  tt);
    }
    #pragma unroll
    for (int off = 16; off > 0; off >>= 1) {
        dot += __shfl_down_sync(0xffffffffu, dot, off);
        kk  += __shfl_down_sync(0xffffffffu, kk,  off);
        tt  += __shfl_down_sync(0xffffffffu, tt,  off);
    }
    if (lane == 0) {
        float denom = fmaxf(sqrtf(tt) * sqrtf(kk), 1e-6f);
        s_cos[warp] = dot / denom;
    }
    __syncthreads();

    if (threadIdx.x == 0) {
        float mx = -1e30f;
        #pragma unroll
        for (int m = 0; m < M_SLOTS; m++) mx = fmaxf(mx, s_cos[m]);
        float e[M_SLOTS];
        float sum = 0.f;
        #pragma unroll
        for (int m = 0; m < M_SLOTS; m++) {
            e[m] = __expf(s_cos[m] - mx);
            sum += e[m];
        }
        float inv = 1.0f / sum;
        #pragma unroll
        for (int m = 0; m < M_SLOTS; m++) g_w[m] = e[m] * inv;
    }
}

// ---------------------------------------------------------------------------
// Kernel 2 (fused, PDL secondary): one grid covers both V0 and V1 segments.
// Launched with programmatic stream serialization so it overlaps with
// weights_kernel: all 16 V-loads are issued BEFORE the grid-dependency sync
// (they don't depend on g_w); only the FMA stage waits for the weights.
// ---------------------------------------------------------------------------
__global__ void __launch_bounds__(256) wsum_fused_kernel(
        const float4* __restrict__ V0,
        const float4* __restrict__ V1,
        float4* __restrict__ out,
        int nv4_0, int nv4_1) {
    int i = blockIdx.x * blockDim.x + threadIdx.x;

    const float4* __restrict__ V;
    float4* __restrict__ dst;
    int idx, stride;
    if (i < nv4_0) {
        V = V0; idx = i; stride = nv4_0; dst = out + i;
    } else {
        int j = i - nv4_0;
        if (j >= nv4_1) return;
        V = V1; idx = j; stride = nv4_1; dst = out + nv4_0 + j;
    }

    // Issue all 16 independent 128-bit loads up front (MLP=16).
    float4 v[M_SLOTS];
    #pragma unroll
    for (int m = 0; m < M_SLOTS; m++)
        v[m] = V[(size_t)m * (size_t)stride + (size_t)idx];

    // Wait for weights_kernel (PDL dependency) only now.
#if __CUDA_ARCH__ >= 900
    cudaGridDependencySynchronize();
#endif

    float4 acc = make_float4(0.f, 0.f, 0.f, 0.f);
    #pragma unroll
    for (int m = 0; m < M_SLOTS; m++) {
        float wm = g_w[m];
        acc.x = fmaf(wm, v[m].x, acc.x);
        acc.y = fmaf(wm, v[m].y, acc.y);
        acc.z = fmaf(wm, v[m].z, acc.z);
        acc.w = fmaf(wm, v[m].w, acc.w);
    }
    *dst = acc;
}

// ---------------------------------------------------------------------------
// Launch contract
// Inputs (metadata order): task_emb [1,1024] f32, K_memory [16,1024] f32,
//                          V0 [16,1024,1024] f32, V1 [16,1024,4096] f32
// Output: rec0 [1024,1024] f32 followed by rec1 [1024,4096] f32
// ---------------------------------------------------------------------------
extern "C" void kernel_launch(void* const* d_in, const int* in_sizes, int n_in,
                              void* d_out, int out_size) {
    const float* task_emb = (const float*)d_in[0];
    const float* K_memory = (const float*)d_in[1];
    const float* V0       = (const float*)d_in[2];
    const float* V1       = (const float*)d_in[3];
    float* out = (float*)d_out;

    const int n0 = in_sizes[2] / M_SLOTS;   // 1024*1024
    const int n1 = in_sizes[3] / M_SLOTS;   // 1024*4096
    const int nv4_0 = n0 / 4;
    const int nv4_1 = n1 / 4;
    const int total = nv4_0 + nv4_1;        // 1310720 -> exactly 5120 blocks

    weights_kernel<<<1, 512>>>(task_emb, K_memory);

    // Secondary launch with programmatic stream serialization (PDL):
    // starts while weights_kernel is still running; the in-kernel
    // cudaGridDependencySynchronize() provides the ordering on g_w.
    cudaLaunchConfig_t cfg = {};
    cfg.gridDim  = dim3((unsigned)((total + 255) / 256));
    cfg.blockDim = dim3(256);
    cfg.dynamicSmemBytes = 0;
    cfg.stream = 0;  // legacy default stream (same one <<<>>> targets)

    cudaLaunchAttribute attrs[1];
    attrs[0].id = cudaLaunchAttributeProgrammaticStreamSerialization;
    attrs[0].val.programmaticStreamSerializationAllowed = 1;
    cfg.attrs = attrs;
    cfg.numAttrs = 1;

    cudaLaunchKernelEx(&cfg, wsum_fused_kernel,
                       (const float4*)V0, (const float4*)V1,
                       (float4*)out, nv4_0, nv4_1);
}

// round 5
// speedup vs baseline: 1.0463x; 1.0054x over previous
#include <cuda_runtime.h>

#define M_SLOTS 16
#define KEY_DIM 1024

// softmax weights, produced by weights_kernel, consumed by wsum_fused_kernel
__device__ float g_w[M_SLOTS];

// ---------------------------------------------------------------------------
// Kernel 1 (PDL primary): cosine similarity + softmax over 16 memory slots.
// Fires the programmatic launch trigger IMMEDIATELY so the secondary grid
// can start issuing its V-loads while this kernel runs.
// ---------------------------------------------------------------------------
__global__ void __launch_bounds__(512) weights_kernel(
        const float* __restrict__ task_emb,
        const float* __restrict__ K_memory) {
#if __CUDA_ARCH__ >= 900
    cudaTriggerProgrammaticLaunchCompletion();
#endif
    __shared__ float s_cos[M_SLOTS];
    const int warp = threadIdx.x >> 5;
    const int lane = threadIdx.x & 31;

    const float4* t4 = (const float4*)task_emb;                 // 256 float4
    const float4* k4 = (const float4*)(K_memory + warp * KEY_DIM);

    float dot = 0.f, kk = 0.f, tt = 0.f;
    #pragma unroll
    for (int j = 0; j < 8; j++) {
        float4 t  = t4[lane + 32 * j];
        float4 km = k4[lane + 32 * j];
        dot = fmaf(t.x, km.x, dot); dot = fmaf(t.y, km.y, dot);
        dot = fmaf(t.z, km.z, dot); dot = fmaf(t.w, km.w, dot);
        kk  = fmaf(km.x, km.x, kk); kk  = fmaf(km.y, km.y, kk);
        kk  = fmaf(km.z, km.z, kk); kk  = fmaf(km.w, km.w, kk);
        tt  = fmaf(t.x,  t.x,  tt); tt  = fmaf(t.y,  t.y,  tt);
        tt  = fmaf(t.z,  t.z,  tt); tt  = fmaf(t.w,  t.w,  tt);
    }
    #pragma unroll
    for (int off = 16; off > 0; off >>= 1) {
        dot += __shfl_down_sync(0xffffffffu, dot, off);
        kk  += __shfl_down_sync(0xffffffffu, kk,  off);
        tt  += __shfl_down_sync(0xffffffffu, tt,  off);
    }
    if (lane == 0) {
        float denom = fmaxf(sqrtf(tt) * sqrtf(kk), 1e-6f);
        s_cos[warp] = dot / denom;
    }
    __syncthreads();

    if (threadIdx.x == 0) {
        float mx = -1e30f;
        #pragma unroll
        for (int m = 0; m < M_SLOTS; m++) mx = fmaxf(mx, s_cos[m]);
        float e[M_SLOTS];
        float sum = 0.f;
        #pragma unroll
        for (int m = 0; m < M_SLOTS; m++) {
            e[m] = __expf(s_cos[m] - mx);
            sum += e[m];
        }
        float inv = 1.0f / sum;
        #pragma unroll
        for (int m = 0; m < M_SLOTS; m++) g_w[m] = e[m] * inv;
    }
}

// ---------------------------------------------------------------------------
// Kernel 2 (PDL secondary): one grid covers both V0 and V1 segments.
// All 16 V-loads are issued and PINNED before the grid-dependency sync via a
// compiler memory barrier (otherwise ptxas sinks them below the sync, as the
// R4 regs=32 SASS proved). Only the g_w FMA stage waits for the primary.
// ---------------------------------------------------------------------------
__global__ void __launch_bounds__(256) wsum_fused_kernel(
        const float4* __restrict__ V0,
        const float4* __restrict__ V1,
        float4* __restrict__ out,
        int nv4_0, int nv4_1) {
    int i = blockIdx.x * blockDim.x + threadIdx.x;

    const float4* __restrict__ V;
    float4* __restrict__ dst;
    int idx, stride;
    if (i < nv4_0) {
        V = V0; idx = i; stride = nv4_0; dst = out + i;
    } else {
        int j = i - nv4_0;
        if (j >= nv4_1) return;
        V = V1; idx = j; stride = nv4_1; dst = out + nv4_0 + j;
    }

    // Issue all 16 independent 128-bit loads up front (MLP=16).
    float4 v[M_SLOTS];
    #pragma unroll
    for (int m = 0; m < M_SLOTS; m++)
        v[m] = V[(size_t)m * (size_t)stride + (size_t)idx];

    // Keep the loads above the dependency sync.
    asm volatile("" ::: "memory");

    // Wait for weights_kernel completion (g_w visible) only now.
#if __CUDA_ARCH__ >= 900
    cudaGridDependencySynchronize();
#endif

    float4 acc = make_float4(0.f, 0.f, 0.f, 0.f);
    #pragma unroll
    for (int m = 0; m < M_SLOTS; m++) {
        float wm = g_w[m];
        acc.x = fmaf(wm, v[m].x, acc.x);
        acc.y = fmaf(wm, v[m].y, acc.y);
        acc.z = fmaf(wm, v[m].z, acc.z);
        acc.w = fmaf(wm, v[m].w, acc.w);
    }
    *dst = acc;
}

// ---------------------------------------------------------------------------
// Launch contract
// Inputs (metadata order): task_emb [1,1024] f32, K_memory [16,1024] f32,
//                          V0 [16,1024,1024] f32, V1 [16,1024,4096] f32
// Output: rec0 [1024,1024] f32 followed by rec1 [1024,4096] f32
// ---------------------------------------------------------------------------
extern "C" void kernel_launch(void* const* d_in, const int* in_sizes, int n_in,
                              void* d_out, int out_size) {
    const float* task_emb = (const float*)d_in[0];
    const float* K_memory = (const float*)d_in[1];
    const float* V0       = (const float*)d_in[2];
    const float* V1       = (const float*)d_in[3];
    float* out = (float*)d_out;

    const int n0 = in_sizes[2] / M_SLOTS;   // 1024*1024
    const int n1 = in_sizes[3] / M_SLOTS;   // 1024*4096
    const int nv4_0 = n0 / 4;
    const int nv4_1 = n1 / 4;
    const int total = nv4_0 + nv4_1;        // 1310720 -> exactly 5120 blocks

    weights_kernel<<<1, 512>>>(task_emb, K_memory);

    // Secondary launch with programmatic stream serialization (PDL).
    cudaLaunchConfig_t cfg = {};
    cfg.gridDim  = dim3((unsigned)((total + 255) / 256));
    cfg.blockDim = dim3(256);
    cfg.dynamicSmemBytes = 0;
    cfg.stream = 0;  // legacy default stream (same one <<<>>> targets)

    cudaLaunchAttribute attrs[1];
    attrs[0].id = cudaLaunchAttributeProgrammaticStreamSerialization;
    attrs[0].val.programmaticStreamSerializationAllowed = 1;
    cfg.attrs = attrs;
    cfg.numAttrs = 1;

    cudaLaunchKernelEx(&cfg, wsum_fused_kernel,
                       (const float4*)V0, (const float4*)V1,
                       (float4*)out, nv4_0, nv4_1);
}